// round 1
// baseline (speedup 1.0000x reference)
#include <cuda_runtime.h>
#include <math.h>

// Problem constants
#define NB 8
#define NHH 64
#define NWW 64
#define NL 4096          // H*W
#define NC 256           // C = D = 256
#define NCAT 1280        // 5*C channels in concat

// ---------------- scratch (device globals: allocation-free) ----------------
__device__ float g_cat[(size_t)NB * NCAT * NL];   // [a|b|b1|b2|attn] NCHW, 168 MB
__device__ float g_tmp[(size_t)NB * NC * NL];     // intermediate conv buffer
__device__ float g_P[(size_t)NB * NL * 352];      // fused proj out: [b][l][352] (256 val | 64 off | 32 aw)
__device__ float g_attn[(size_t)NB * NL * NC];    // deform-attn pre-projection [b][l][256]
__device__ float g_WcatT[352 * 256];              // concatenated proj weights, [j][c]
__device__ float g_bcat[352];

__device__ __forceinline__ float silu_f(float x) { return x / (1.0f + expf(-x)); }

// ---------------- weight prep: concat + transpose proj weights ----------------
__global__ void prep_wcat_kernel(const float* __restrict__ vw, const float* __restrict__ vb,
                                 const float* __restrict__ ow, const float* __restrict__ ob,
                                 const float* __restrict__ aww, const float* __restrict__ awb)
{
    int j = blockIdx.x;     // 0..351
    int c = threadIdx.x;    // 0..255
    float v;
    if (j < 256)       v = vw[c * 256 + j];
    else if (j < 320)  v = ow[c * 64 + (j - 256)];
    else               v = aww[c * 32 + (j - 320)];
    g_WcatT[j * 256 + c] = v;
    if (c == 0)
        g_bcat[j] = (j < 256) ? vb[j] : ((j < 320) ? ob[j - 256] : awb[j - 320]);
}

// ---------------- generic strided SGEMM: C[m,n] = sum_k A[m,k]*B[k,n] ----------------
// Tile 64x64, BK=8, 128 threads, 4m x 8n per thread. N is always 4096 (full tiles).
// K must be a multiple of 8. M may be ragged (guarded).
__global__ void sgemm_kernel(const float* __restrict__ A,
                             const float* __restrict__ Bm,
                             float* __restrict__ Cm,
                             int M, int K,
                             int sAm, int sAk,
                             long long bStrB, int sBk, int sBn,
                             long long bStrC, int sCm, int sCn,
                             const float* __restrict__ bias, int act)
{
    __shared__ __align__(16) float sA[8][68];
    __shared__ __align__(16) float sB[8][68];
    const float* Bp = Bm + (long long)blockIdx.z * bStrB;
    float*       Cp = Cm + (long long)blockIdx.z * bStrC;
    int m0 = blockIdx.y * 64, n0 = blockIdx.x * 64;
    int tid = threadIdx.x;
    int ng = tid & 7, mg = tid >> 3;

    float acc[4][8];
#pragma unroll
    for (int i = 0; i < 4; i++)
#pragma unroll
        for (int j = 0; j < 8; j++) acc[i][j] = 0.f;

    for (int k0 = 0; k0 < K; k0 += 8) {
#pragma unroll
        for (int t = 0; t < 4; t++) {
            int i = tid + t * 128;
            int m, k;
            if (sAk == 1) { k = i & 7; m = i >> 3; }      // row-major A: k fastest
            else          { m = i & 63; k = i >> 6; }     // transposed A: m fastest
            int mm = m0 + m;
            sA[k][m] = (mm < M) ? A[(long long)mm * sAm + (long long)(k0 + k) * sAk] : 0.f;
        }
#pragma unroll
        for (int t = 0; t < 4; t++) {
            int i = tid + t * 128;
            int n, k;
            if (sBn == 1) { n = i & 63; k = i >> 6; }
            else          { k = i & 7;  n = i >> 3; }
            sB[k][n] = Bp[(long long)(k0 + k) * sBk + (long long)(n0 + n) * sBn];
        }
        __syncthreads();
#pragma unroll
        for (int kk = 0; kk < 8; kk++) {
            float4 a  = *(const float4*)&sA[kk][mg * 4];
            float4 b0 = *(const float4*)&sB[kk][ng * 4];
            float4 b1 = *(const float4*)&sB[kk][32 + ng * 4];
            float av[4] = {a.x, a.y, a.z, a.w};
            float bv[8] = {b0.x, b0.y, b0.z, b0.w, b1.x, b1.y, b1.z, b1.w};
#pragma unroll
            for (int i = 0; i < 4; i++)
#pragma unroll
                for (int j = 0; j < 8; j++)
                    acc[i][j] = fmaf(av[i], bv[j], acc[i][j]);
        }
        __syncthreads();
    }

#pragma unroll
    for (int i = 0; i < 4; i++) {
        int mm = m0 + mg * 4 + i;
        if (mm >= M) continue;
        float bb = bias ? bias[mm] : 0.f;
#pragma unroll
        for (int j = 0; j < 8; j++) {
            int nn = n0 + ((j < 4) ? (ng * 4 + j) : (32 + ng * 4 + (j - 4)));
            float v = acc[i][j] + bb;
            if (act) v = silu_f(v);
            Cp[(long long)mm * sCm + (long long)nn * sCn] = v;
        }
    }
}

// ---------------- direct 3x3 conv (256->256, pad 1) + SiLU ----------------
// grid: (64 rows, 4 co-tiles, 8 batch); block 128 threads.
// Block computes 64 output channels x one full row (64 px).
// Thread: 4 co x 8 px; register row-reuse across kx -> 96 FMA per ~7 LDS.
__global__ void conv3x3_silu_kernel(const float* __restrict__ src,
                                    float* __restrict__ dst,
                                    const float* __restrict__ w,
                                    long long srcStride, long long dstStride)
{
    __shared__ __align__(16) float sIn[8][3][68];   // [ci][row][col], col c <-> x = c-1
    __shared__ __align__(16) float sW[8][9][64];    // [ci][tap][co]
    int y   = blockIdx.x;
    int co0 = blockIdx.y * 64;
    const float* sp = src + (long long)blockIdx.z * srcStride;
    float*       dp = dst + (long long)blockIdx.z * dstStride;
    int tid = threadIdx.x;
    int pxg = tid & 7, cog = tid >> 3;  // cog 0..15
    int px0 = pxg * 8;

    float acc[4][8];
#pragma unroll
    for (int i = 0; i < 4; i++)
#pragma unroll
        for (int j = 0; j < 8; j++) acc[i][j] = 0.f;

    for (int ci0 = 0; ci0 < 256; ci0 += 8) {
        // input patch: 8 ci x 3 rows x 66 cols (zero-padded)
        for (int i = tid; i < 8 * 3 * 66; i += 128) {
            int ci  = i / 198;
            int r2  = i - ci * 198;
            int row = r2 / 66;
            int col = r2 - row * 66;
            int yin = y + row - 1, xin = col - 1;
            float v = 0.f;
            if ((unsigned)yin < 64u && (unsigned)xin < 64u)
                v = sp[((long long)(ci0 + ci) << 12) + (yin << 6) + xin];
            sIn[ci][row][col] = v;
        }
        // weights: 64 co x (8 ci x 9 taps); contiguous 72-float runs per co
        for (int i = tid; i < 64 * 72; i += 128) {
            int co = i / 72;
            int r  = i - co * 72;          // r = ci*9 + tap
            int ci = r / 9;
            sW[ci][r - ci * 9][co] = w[((long long)(co0 + co) * 256 + ci0) * 9 + r];
        }
        __syncthreads();
#pragma unroll
        for (int ci = 0; ci < 8; ci++) {
#pragma unroll
            for (int ky = 0; ky < 3; ky++) {
                float4 t0 = *(const float4*)&sIn[ci][ky][px0];
                float4 t1 = *(const float4*)&sIn[ci][ky][px0 + 4];
                float rr[10] = {t0.x, t0.y, t0.z, t0.w, t1.x, t1.y, t1.z, t1.w,
                                sIn[ci][ky][px0 + 8], sIn[ci][ky][px0 + 9]};
#pragma unroll
                for (int kx = 0; kx < 3; kx++) {
                    float4 wv = *(const float4*)&sW[ci][ky * 3 + kx][cog * 4];
                    float wa[4] = {wv.x, wv.y, wv.z, wv.w};
#pragma unroll
                    for (int i = 0; i < 4; i++)
#pragma unroll
                        for (int j = 0; j < 8; j++)
                            acc[i][j] = fmaf(wa[i], rr[j + kx], acc[i][j]);
                }
            }
        }
        __syncthreads();
    }

#pragma unroll
    for (int i = 0; i < 4; i++) {
        int co = co0 + cog * 4 + i;
#pragma unroll
        for (int j = 0; j < 8; j++)
            dp[((long long)co << 12) + (y << 6) + px0 + j] = silu_f(acc[i][j]);
    }
}

// ---------------- deformable sampling: one warp per (b,l,h), lane = dh ----------------
__global__ void msda_kernel(const float* __restrict__ P,
                            const float* __restrict__ rb,
                            float* __restrict__ outp)
{
    int warp = threadIdx.x >> 5;
    int lane = threadIdx.x & 31;
    long long gw = (long long)blockIdx.x * 8 + warp;  // 0 .. 262143
    int h = (int)(gw & 7);
    long long bl = gw >> 3;               // b*4096 + l
    long long b  = bl >> 12;
    const float* Pl = P + bl * 352;
    const float* Vb = P + b * (long long)NL * 352;
    float rbx = rb[bl * 2 + 0];
    float rby = rb[bl * 2 + 1];

    // softmax over 4 attention logits
    float lg[4];
    float mx = -1e30f;
#pragma unroll
    for (int p = 0; p < 4; p++) { lg[p] = Pl[320 + h * 4 + p]; mx = fmaxf(mx, lg[p]); }
    float s = 0.f;
#pragma unroll
    for (int p = 0; p < 4; p++) { lg[p] = expf(lg[p] - mx); s += lg[p]; }
    float inv = 1.f / s;

    int hoff = h * 32 + lane;
    float acc = 0.f;
#pragma unroll
    for (int p = 0; p < 4; p++) {
        float ox = Pl[256 + h * 8 + p * 2 + 0];
        float oy = Pl[256 + h * 8 + p * 2 + 1];
        float gx = (rbx + ox * (1.f / 64.f)) * 64.f - 0.5f;
        float gy = (rby + oy * (1.f / 64.f)) * 64.f - 0.5f;
        float x0f = floorf(gx), y0f = floorf(gy);
        int x0 = (int)x0f, y0 = (int)y0f;
        float wx1 = gx - x0f, wy1 = gy - y0f;
        float wx0 = 1.f - wx1, wy0 = 1.f - wy1;

        float v00 = 0.f, v10 = 0.f, v01 = 0.f, v11 = 0.f;
        if ((unsigned)x0       < 64u && (unsigned)y0       < 64u) v00 = Vb[(long long)(y0 * 64 + x0) * 352 + hoff];
        if ((unsigned)(x0 + 1) < 64u && (unsigned)y0       < 64u) v10 = Vb[(long long)(y0 * 64 + x0 + 1) * 352 + hoff];
        if ((unsigned)x0       < 64u && (unsigned)(y0 + 1) < 64u) v01 = Vb[(long long)((y0 + 1) * 64 + x0) * 352 + hoff];
        if ((unsigned)(x0 + 1) < 64u && (unsigned)(y0 + 1) < 64u) v11 = Vb[(long long)((y0 + 1) * 64 + x0 + 1) * 352 + hoff];

        float sv = v00 * (wx0 * wy0) + v10 * (wx1 * wy0) + v01 * (wx0 * wy1) + v11 * (wx1 * wy1);
        acc = fmaf(lg[p] * inv, sv, acc);
    }
    outp[bl * 256 + hoff] = acc;
}

// ---------------- launch ----------------
extern "C" void kernel_launch(void* const* d_in, const int* in_sizes, int n_in,
                              void* d_out, int out_size)
{
    const float* x       = (const float*)d_in[0];
    const float* rb      = (const float*)d_in[1];
    // d_in[2] value_shapes (int32) = [[64,64]] : hardcoded
    const float* cv1_w   = (const float*)d_in[3];
    const float* m0c1    = (const float*)d_in[4];
    const float* m0c2    = (const float*)d_in[5];
    const float* m1c1    = (const float*)d_in[6];
    const float* m1c2    = (const float*)d_in[7];
    const float* vproj_w = (const float*)d_in[8];
    const float* vproj_b = (const float*)d_in[9];
    const float* off_w   = (const float*)d_in[10];
    const float* off_b   = (const float*)d_in[11];
    const float* aw_w    = (const float*)d_in[12];
    const float* aw_b    = (const float*)d_in[13];
    const float* out_w   = (const float*)d_in[14];
    const float* out_b   = (const float*)d_in[15];
    const float* cv2_w   = (const float*)d_in[16];
    float* out = (float*)d_out;

    float *cat, *tmp, *P, *attn, *WcatT, *bcat;
    cudaGetSymbolAddress((void**)&cat,   g_cat);
    cudaGetSymbolAddress((void**)&tmp,   g_tmp);
    cudaGetSymbolAddress((void**)&P,     g_P);
    cudaGetSymbolAddress((void**)&attn,  g_attn);
    cudaGetSymbolAddress((void**)&WcatT, g_WcatT);
    cudaGetSymbolAddress((void**)&bcat,  g_bcat);

    const long long CATS = (long long)NCAT * NL;   // per-batch stride of g_cat

    // 0) pack projection weights [vproj|off|aw]^T
    prep_wcat_kernel<<<352, 256>>>(vproj_w, vproj_b, off_w, off_b, aw_w, aw_b);

    // 1) cv1 (1x1, 512->512, SiLU) -> cat channels [0,512)
    sgemm_kernel<<<dim3(64, 8, NB), 128>>>(cv1_w, x, cat, 512, 512,
        512, 1, 512LL * NL, NL, 1, CATS, NL, 1, nullptr, 1);

    // 2) bottleneck convs (each 3x3 256->256 + SiLU)
    dim3 cgrid(64, 4, NB);
    conv3x3_silu_kernel<<<cgrid, 128>>>(cat + 256LL * NL, tmp,              m0c1, CATS, (long long)NC * NL);
    conv3x3_silu_kernel<<<cgrid, 128>>>(tmp,              cat + 512LL * NL, m0c2, (long long)NC * NL, CATS);
    conv3x3_silu_kernel<<<cgrid, 128>>>(cat + 512LL * NL, tmp,              m1c1, CATS, (long long)NC * NL);
    conv3x3_silu_kernel<<<cgrid, 128>>>(tmp,              cat + 768LL * NL, m1c2, (long long)NC * NL, CATS);

    // 3) fused projection: P[b][l][352] = q @ [vproj|off|aw] + bias   (q = b2^T)
    sgemm_kernel<<<dim3(64, 6, NB), 128>>>(WcatT, cat + 768LL * NL, P, 352, 256,
        256, 1, CATS, NL, 1, (long long)NL * 352, 1, 352, bcat, 0);

    // 4) deformable bilinear sampling + attention weighting
    msda_kernel<<<32768, 256>>>(P, rb, attn);

    // 5) output projection -> cat channels [1024,1280) (NCHW layout)
    sgemm_kernel<<<dim3(64, 4, NB), 128>>>(out_w, attn, cat + 1024LL * NL, 256, 256,
        1, 256, (long long)NL * 256, 1, 256, CATS, NL, 1, out_b, 0);

    // 6) cv2 (1x1, 1280->512, SiLU) over the concat
    sgemm_kernel<<<dim3(64, 8, NB), 128>>>(cv2_w, cat, out, 512, 1280,
        1280, 1, CATS, NL, 1, 512LL * NL, NL, 1, nullptr, 1);
}

// round 2
// speedup vs baseline: 1.2617x; 1.2617x over previous
#include <cuda_runtime.h>
#include <math.h>

#define NB 8
#define NL 4096
#define NC 256
#define NCAT 1280

// ---------------- scratch ----------------
__device__ __align__(128) float g_cat[(size_t)NB * NCAT * NL];
__device__ __align__(128) float g_tmp[(size_t)NB * NC * NL];
__device__ __align__(128) float g_P[(size_t)NB * NL * 352];
__device__ __align__(128) float g_attn[(size_t)NB * NC * NL];   // NCHW [b][d][l]
__device__ __align__(128) float g_WcatT[352 * 256];
__device__ float g_bcat[352];
__device__ __align__(128) float g_wt[4][2304 * 256];            // conv weights [ci*9+tap][co]

__device__ __forceinline__ float silu_f(float x) { return x / (1.0f + expf(-x)); }

// ---------------- prep: concat proj weights ----------------
__global__ void prep_wcat_kernel(const float* __restrict__ vw, const float* __restrict__ vb,
                                 const float* __restrict__ ow, const float* __restrict__ ob,
                                 const float* __restrict__ aww, const float* __restrict__ awb)
{
    int j = blockIdx.x, c = threadIdx.x;
    float v;
    if (j < 256)       v = vw[c * 256 + j];
    else if (j < 320)  v = ow[c * 64 + (j - 256)];
    else               v = aww[c * 32 + (j - 320)];
    g_WcatT[j * 256 + c] = v;
    if (c == 0)
        g_bcat[j] = (j < 256) ? vb[j] : ((j < 320) ? ob[j - 256] : awb[j - 320]);
}

// ---------------- prep: transpose conv weights to [ci*9+tap][co] ----------------
__global__ void transp_w_kernel(const float* __restrict__ w, float* __restrict__ o)
{
    int r = blockIdx.x;               // 0..2303 = ci*9 + tap
    int ci = r / 9, tap = r - ci * 9;
    int co = threadIdx.x;             // 0..255
    o[r * 256 + co] = w[(co * 256 + ci) * 9 + tap];
}

// ---------------- SGEMM v2: tile 64m x 128n, BK=16, 128 thr, 8x8/thread ----------------
__global__ void __launch_bounds__(128, 4)
sgemm_v2(const float* __restrict__ A, const float* __restrict__ Bm, float* __restrict__ Cm,
         int M, int K,
         int sAm, int sAk,                 // exactly one == 1
         long long bStrB, int sBk,         // B n-stride == 1
         long long bStrC, int sCm, int sCn,// exactly one == 1
         const float* __restrict__ bias, int act)
{
    __shared__ __align__(16) float sA[16][68];
    __shared__ __align__(16) float sB[16][128];
    const float* Bp = Bm + (long long)blockIdx.z * bStrB;
    float*       Cp = Cm + (long long)blockIdx.z * bStrC;
    int m0 = blockIdx.y * 64, n0 = blockIdx.x * 128;
    int tid = threadIdx.x;
    int ng = tid & 15, mg = tid >> 4;

    float acc[8][8];
#pragma unroll
    for (int i = 0; i < 8; i++)
#pragma unroll
        for (int j = 0; j < 8; j++) acc[i][j] = 0.f;

    const float4 z4 = make_float4(0.f, 0.f, 0.f, 0.f);

    for (int k0 = 0; k0 < K; k0 += 16) {
        float4 av[2], bv[4];
        if (sAk == 1) {
#pragma unroll
            for (int t = 0; t < 2; t++) {
                int f = tid + t * 128;
                int m = f >> 2, kq = f & 3;
                int mm = m0 + m;
                av[t] = (mm < M) ? *(const float4*)&A[(long long)mm * sAm + k0 + kq * 4] : z4;
            }
        } else {
#pragma unroll
            for (int t = 0; t < 2; t++) {
                int f = tid + t * 128;
                int kk = f >> 4, mq = f & 15;
                int mm = m0 + mq * 4;
                av[t] = (mm < M) ? *(const float4*)&A[(long long)(k0 + kk) * sAk + mm] : z4;
            }
        }
#pragma unroll
        for (int t = 0; t < 4; t++) {
            int f = tid + t * 128;
            int kk = f >> 5, nq = f & 31;
            bv[t] = *(const float4*)&Bp[(long long)(k0 + kk) * sBk + n0 + nq * 4];
        }
        __syncthreads();
        if (sAk == 1) {
#pragma unroll
            for (int t = 0; t < 2; t++) {
                int f = tid + t * 128;
                int m = f >> 2, kq = f & 3;
                sA[kq * 4 + 0][m] = av[t].x;
                sA[kq * 4 + 1][m] = av[t].y;
                sA[kq * 4 + 2][m] = av[t].z;
                sA[kq * 4 + 3][m] = av[t].w;
            }
        } else {
#pragma unroll
            for (int t = 0; t < 2; t++) {
                int f = tid + t * 128;
                int kk = f >> 4, mq = f & 15;
                *(float4*)&sA[kk][mq * 4] = av[t];
            }
        }
#pragma unroll
        for (int t = 0; t < 4; t++) {
            int f = tid + t * 128;
            int kk = f >> 5, nq = f & 31;
            *(float4*)&sB[kk][nq * 4] = bv[t];
        }
        __syncthreads();
#pragma unroll
        for (int kk = 0; kk < 16; kk++) {
            float4 a0 = *(const float4*)&sA[kk][mg * 8];
            float4 a1 = *(const float4*)&sA[kk][mg * 8 + 4];
            float4 b0 = *(const float4*)&sB[kk][ng * 8];
            float4 b1 = *(const float4*)&sB[kk][ng * 8 + 4];
            float am[8] = {a0.x, a0.y, a0.z, a0.w, a1.x, a1.y, a1.z, a1.w};
            float bn[8] = {b0.x, b0.y, b0.z, b0.w, b1.x, b1.y, b1.z, b1.w};
#pragma unroll
            for (int i = 0; i < 8; i++)
#pragma unroll
                for (int j = 0; j < 8; j++)
                    acc[i][j] = fmaf(am[i], bn[j], acc[i][j]);
        }
        __syncthreads();
    }

    if (sCn == 1) {
#pragma unroll
        for (int i = 0; i < 8; i++) {
            int mm = m0 + mg * 8 + i;
            if (mm >= M) continue;
            float bb = bias ? bias[mm] : 0.f;
            float v[8];
#pragma unroll
            for (int j = 0; j < 8; j++) {
                float t = acc[i][j] + bb;
                v[j] = act ? silu_f(t) : t;
            }
            float* cp = &Cp[(long long)mm * sCm + n0 + ng * 8];
            *(float4*)cp       = make_float4(v[0], v[1], v[2], v[3]);
            *(float4*)(cp + 4) = make_float4(v[4], v[5], v[6], v[7]);
        }
    } else {
        // m-contiguous store (sCm == 1)
        float bm[8];
#pragma unroll
        for (int i = 0; i < 8; i++) {
            int mm = m0 + mg * 8 + i;
            bm[i] = (bias && mm < M) ? bias[mm] : 0.f;
        }
        if (m0 + mg * 8 < M) {
#pragma unroll
            for (int j = 0; j < 8; j++) {
                int nn = n0 + ng * 8 + j;
                float v[8];
#pragma unroll
                for (int i = 0; i < 8; i++) {
                    float t = acc[i][j] + bm[i];
                    v[i] = act ? silu_f(t) : t;
                }
                float* cp = &Cp[(long long)nn * sCn + m0 + mg * 8];
                *(float4*)cp       = make_float4(v[0], v[1], v[2], v[3]);
                *(float4*)(cp + 4) = make_float4(v[4], v[5], v[6], v[7]);
            }
        }
    }
}

// ---------------- conv 3x3 v2: block 64co x (2 rows x 64px), 128 thr, 8co x 8px/thread ----------------
__global__ void __launch_bounds__(128, 4)
conv3x3_v2(const float* __restrict__ src, float* __restrict__ dst,
           const float* __restrict__ wt,            // transposed [ci*9+tap][256]
           long long srcStride, long long dstStride)
{
    __shared__ __align__(16) float sIn[8][4][68];   // [ci][row][col]; col c <-> x = c-1
    __shared__ __align__(16) float sW[8 * 9][64];   // [ci*9+tap][co]
    int y0  = blockIdx.x * 2;
    int co0 = blockIdx.y * 64;
    const float* sp = src + (long long)blockIdx.z * srcStride;
    float*       dp = dst + (long long)blockIdx.z * dstStride;
    int tid = threadIdx.x;
    int pxg = tid & 15;           // row = pxg>>3, colblk = pxg&7
    int cog = tid >> 4;           // 0..7 -> 8 co each
    int rowsel = pxg >> 3;
    int px0 = (pxg & 7) * 8;

    // zero the constant padding columns (x=-1 -> col 0, x=64 -> col 65) once
    if (tid < 64) {
        int ci = tid >> 3, rr_ = (tid >> 1) & 3, side = tid & 1;
        sIn[ci][rr_][side ? 65 : 0] = 0.f;
    }

    float acc[8][8];
#pragma unroll
    for (int i = 0; i < 8; i++)
#pragma unroll
        for (int j = 0; j < 8; j++) acc[i][j] = 0.f;

    const float4 z4 = make_float4(0.f, 0.f, 0.f, 0.f);

    for (int ci0 = 0; ci0 < 256; ci0 += 8) {
        // stage global loads in registers (overlaps previous chunk's compute)
        float4 ir[4];
#pragma unroll
        for (int t = 0; t < 4; t++) {
            int f = tid + t * 128;          // 0..511
            int ci = f >> 6;
            int rr_ = (f >> 4) & 3;
            int cq = f & 15;
            int yin = y0 - 1 + rr_;
            ir[t] = ((unsigned)yin < 64u)
                  ? *(const float4*)&sp[((long long)(ci0 + ci) << 12) + (yin << 6) + cq * 4]
                  : z4;
        }
        float4 wr[9];
#pragma unroll
        for (int t = 0; t < 9; t++) {
            int f = tid + t * 128;          // 0..1151
            int rrow = f >> 4;              // 0..71
            int cq = f & 15;
            wr[t] = *(const float4*)&wt[(long long)(ci0 * 9 + rrow) * 256 + co0 + cq * 4];
        }
        __syncthreads();
#pragma unroll
        for (int t = 0; t < 4; t++) {
            int f = tid + t * 128;
            int ci = f >> 6;
            int rr_ = (f >> 4) & 3;
            int cq = f & 15;
            float* p = &sIn[ci][rr_][1 + cq * 4];
            p[0] = ir[t].x; p[1] = ir[t].y; p[2] = ir[t].z; p[3] = ir[t].w;
        }
#pragma unroll
        for (int t = 0; t < 9; t++) {
            int f = tid + t * 128;
            int rrow = f >> 4;
            int cq = f & 15;
            *(float4*)&sW[rrow][cq * 4] = wr[t];
        }
        __syncthreads();

#pragma unroll 1
        for (int ci = 0; ci < 8; ci++) {
#pragma unroll
            for (int ky = 0; ky < 3; ky++) {
                const float* rp = &sIn[ci][rowsel + ky][px0];
                float4 r0 = *(const float4*)rp;
                float4 r1 = *(const float4*)(rp + 4);
                float rr[10] = {r0.x, r0.y, r0.z, r0.w, r1.x, r1.y, r1.z, r1.w, rp[8], rp[9]};
#pragma unroll
                for (int kx = 0; kx < 3; kx++) {
                    float4 wa = *(const float4*)&sW[ci * 9 + ky * 3 + kx][cog * 8];
                    float4 wb = *(const float4*)&sW[ci * 9 + ky * 3 + kx][cog * 8 + 4];
                    float wv[8] = {wa.x, wa.y, wa.z, wa.w, wb.x, wb.y, wb.z, wb.w};
#pragma unroll
                    for (int i = 0; i < 8; i++)
#pragma unroll
                        for (int j = 0; j < 8; j++)
                            acc[i][j] = fmaf(wv[i], rr[j + kx], acc[i][j]);
                }
            }
        }
        __syncthreads();
    }

    int y = y0 + rowsel;
#pragma unroll
    for (int i = 0; i < 8; i++) {
        int co = co0 + cog * 8 + i;
        float v[8];
#pragma unroll
        for (int j = 0; j < 8; j++) v[j] = silu_f(acc[i][j]);
        float* cp = &dp[((long long)co << 12) + (y << 6) + px0];
        *(float4*)cp       = make_float4(v[0], v[1], v[2], v[3]);
        *(float4*)(cp + 4) = make_float4(v[4], v[5], v[6], v[7]);
    }
}

// ---------------- deformable sampling: one warp per (b,l,h), lane = dh ----------------
__global__ void msda_kernel(const float* __restrict__ P,
                            const float* __restrict__ rb,
                            float* __restrict__ outp)
{
    int warp = threadIdx.x >> 5;
    int lane = threadIdx.x & 31;
    long long gw = (long long)blockIdx.x * 8 + warp;
    int h = (int)(gw & 7);
    long long bl = gw >> 3;               // b*4096 + l
    long long b  = bl >> 12;
    long long l  = bl & 4095;
    const float* Pl = P + bl * 352;
    const float* Vb = P + b * (long long)NL * 352;
    float rbx = rb[bl * 2 + 0];
    float rby = rb[bl * 2 + 1];

    float lg[4];
    float mx = -1e30f;
#pragma unroll
    for (int p = 0; p < 4; p++) { lg[p] = Pl[320 + h * 4 + p]; mx = fmaxf(mx, lg[p]); }
    float s = 0.f;
#pragma unroll
    for (int p = 0; p < 4; p++) { lg[p] = expf(lg[p] - mx); s += lg[p]; }
    float inv = 1.f / s;

    int hoff = h * 32 + lane;
    float acc = 0.f;
#pragma unroll
    for (int p = 0; p < 4; p++) {
        float ox = Pl[256 + h * 8 + p * 2 + 0];
        float oy = Pl[256 + h * 8 + p * 2 + 1];
        float gx = (rbx + ox * (1.f / 64.f)) * 64.f - 0.5f;
        float gy = (rby + oy * (1.f / 64.f)) * 64.f - 0.5f;
        float x0f = floorf(gx), y0f = floorf(gy);
        int x0 = (int)x0f, y0 = (int)y0f;
        float wx1 = gx - x0f, wy1 = gy - y0f;
        float wx0 = 1.f - wx1, wy0 = 1.f - wy1;

        float v00 = 0.f, v10 = 0.f, v01 = 0.f, v11 = 0.f;
        if ((unsigned)x0       < 64u && (unsigned)y0       < 64u) v00 = Vb[(long long)(y0 * 64 + x0) * 352 + hoff];
        if ((unsigned)(x0 + 1) < 64u && (unsigned)y0       < 64u) v10 = Vb[(long long)(y0 * 64 + x0 + 1) * 352 + hoff];
        if ((unsigned)x0       < 64u && (unsigned)(y0 + 1) < 64u) v01 = Vb[(long long)((y0 + 1) * 64 + x0) * 352 + hoff];
        if ((unsigned)(x0 + 1) < 64u && (unsigned)(y0 + 1) < 64u) v11 = Vb[(long long)((y0 + 1) * 64 + x0 + 1) * 352 + hoff];

        float sv = v00 * (wx0 * wy0) + v10 * (wx1 * wy0) + v01 * (wx0 * wy1) + v11 * (wx1 * wy1);
        acc = fmaf(lg[p] * inv, sv, acc);
    }
    // NCHW output: [b][d][l]
    outp[((long long)b * 256 + hoff) * 4096 + l] = acc;
}

// ---------------- launch ----------------
extern "C" void kernel_launch(void* const* d_in, const int* in_sizes, int n_in,
                              void* d_out, int out_size)
{
    const float* x       = (const float*)d_in[0];
    const float* rb      = (const float*)d_in[1];
    const float* cv1_w   = (const float*)d_in[3];
    const float* m0c1    = (const float*)d_in[4];
    const float* m0c2    = (const float*)d_in[5];
    const float* m1c1    = (const float*)d_in[6];
    const float* m1c2    = (const float*)d_in[7];
    const float* vproj_w = (const float*)d_in[8];
    const float* vproj_b = (const float*)d_in[9];
    const float* off_w   = (const float*)d_in[10];
    const float* off_b   = (const float*)d_in[11];
    const float* aw_w    = (const float*)d_in[12];
    const float* aw_b    = (const float*)d_in[13];
    const float* out_w   = (const float*)d_in[14];
    const float* out_b   = (const float*)d_in[15];
    const float* cv2_w   = (const float*)d_in[16];
    float* out = (float*)d_out;

    float *cat, *tmp, *P, *attn, *WcatT, *bcat, *wtbase;
    cudaGetSymbolAddress((void**)&cat,    g_cat);
    cudaGetSymbolAddress((void**)&tmp,    g_tmp);
    cudaGetSymbolAddress((void**)&P,      g_P);
    cudaGetSymbolAddress((void**)&attn,   g_attn);
    cudaGetSymbolAddress((void**)&WcatT,  g_WcatT);
    cudaGetSymbolAddress((void**)&bcat,   g_bcat);
    cudaGetSymbolAddress((void**)&wtbase, g_wt);

    const long long CATS = (long long)NCAT * NL;
    const long long WTS  = 2304LL * 256;

    // 0) weight prep
    prep_wcat_kernel<<<352, 256>>>(vproj_w, vproj_b, off_w, off_b, aw_w, aw_b);
    transp_w_kernel<<<2304, 256>>>(m0c1, wtbase + 0 * WTS);
    transp_w_kernel<<<2304, 256>>>(m0c2, wtbase + 1 * WTS);
    transp_w_kernel<<<2304, 256>>>(m1c1, wtbase + 2 * WTS);
    transp_w_kernel<<<2304, 256>>>(m1c2, wtbase + 3 * WTS);

    // 1) cv1 (1x1, 512->512, SiLU) -> cat channels [0,512)
    sgemm_v2<<<dim3(32, 8, NB), 128>>>(cv1_w, x, cat, 512, 512,
        512, 1, 512LL * NL, NL, CATS, NL, 1, nullptr, 1);

    // 2) bottleneck convs
    dim3 cgrid(32, 4, NB);
    conv3x3_v2<<<cgrid, 128>>>(cat + 256LL * NL, tmp,              wtbase + 0 * WTS, CATS, (long long)NC * NL);
    conv3x3_v2<<<cgrid, 128>>>(tmp,              cat + 512LL * NL, wtbase + 1 * WTS, (long long)NC * NL, CATS);
    conv3x3_v2<<<cgrid, 128>>>(cat + 512LL * NL, tmp,              wtbase + 2 * WTS, CATS, (long long)NC * NL);
    conv3x3_v2<<<cgrid, 128>>>(tmp,              cat + 768LL * NL, wtbase + 3 * WTS, (long long)NC * NL, CATS);

    // 3) fused projection: P[b][l][352] = q @ [vproj|off|aw] + bias
    sgemm_v2<<<dim3(32, 6, NB), 128>>>(WcatT, cat + 768LL * NL, P, 352, 256,
        256, 1, CATS, NL, (long long)NL * 352, 1, 352, bcat, 0);

    // 4) deformable sampling (writes NCHW attn)
    msda_kernel<<<32768, 256>>>(P, rb, attn);

    // 5) output projection -> cat channels [1024,1280)
    sgemm_v2<<<dim3(32, 4, NB), 128>>>(out_w, attn, cat + 1024LL * NL, 256, 256,
        1, 256, (long long)NC * NL, NL, CATS, NL, 1, out_b, 0);

    // 6) cv2 (1x1, 1280->512, SiLU)
    sgemm_v2<<<dim3(32, 8, NB), 128>>>(cv2_w, cat, out, 512, 1280,
        1280, 1, CATS, NL, 512LL * NL, NL, 1, nullptr, 1);
}

// round 3
// speedup vs baseline: 2.0292x; 1.6083x over previous
#include <cuda_runtime.h>
#include <math.h>

#define NB 8
#define NL 4096
#define NC 256
#define NCAT 1280

// ---------------- scratch ----------------
__device__ __align__(128) float g_cat[(size_t)NB * NCAT * NL];
__device__ __align__(128) float g_tmp[(size_t)NB * NC * NL];
__device__ __align__(128) float g_P[(size_t)NB * NL * 352];
__device__ __align__(128) float g_attn[(size_t)NB * NC * NL];   // NCHW [b][d][l]
__device__ __align__(128) float g_WcatT[352 * 256];
__device__ float g_bcat[352];
__device__ __align__(128) float g_wt[4][2304 * 256];            // conv weights [ci*9+tap][co]

__device__ __forceinline__ float silu_f(float x) { return x / (1.0f + expf(-x)); }

// ---------------- prep: concat proj weights ----------------
__global__ void prep_wcat_kernel(const float* __restrict__ vw, const float* __restrict__ vb,
                                 const float* __restrict__ ow, const float* __restrict__ ob,
                                 const float* __restrict__ aww, const float* __restrict__ awb)
{
    int j = blockIdx.x, c = threadIdx.x;
    float v;
    if (j < 256)       v = vw[c * 256 + j];
    else if (j < 320)  v = ow[c * 64 + (j - 256)];
    else               v = aww[c * 32 + (j - 320)];
    g_WcatT[j * 256 + c] = v;
    if (c == 0)
        g_bcat[j] = (j < 256) ? vb[j] : ((j < 320) ? ob[j - 256] : awb[j - 320]);
}

// ---------------- prep: transpose conv weights to [ci*9+tap][co] ----------------
__global__ void transp_w_kernel(const float* __restrict__ w, float* __restrict__ o)
{
    int r = blockIdx.x;               // 0..2303 = ci*9 + tap
    int ci = r / 9, tap = r - ci * 9;
    int co = threadIdx.x;             // 0..255
    o[r * 256 + co] = w[(co * 256 + ci) * 9 + tap];
}

// ---------------- SGEMM v2: tile 64m x 128n, BK=16, 128 thr, 8x8/thread ----------------
__global__ void __launch_bounds__(128, 4)
sgemm_v2(const float* __restrict__ A, const float* __restrict__ Bm, float* __restrict__ Cm,
         int M, int K,
         int sAm, int sAk,                 // exactly one == 1
         long long bStrB, int sBk,         // B n-stride == 1
         long long bStrC, int sCm, int sCn,// exactly one == 1
         const float* __restrict__ bias, int act)
{
    __shared__ __align__(16) float sA[16][68];
    __shared__ __align__(16) float sB[16][128];
    const float* Bp = Bm + (long long)blockIdx.z * bStrB;
    float*       Cp = Cm + (long long)blockIdx.z * bStrC;
    int m0 = blockIdx.y * 64, n0 = blockIdx.x * 128;
    int tid = threadIdx.x;
    int ng = tid & 15, mg = tid >> 4;

    float acc[8][8];
#pragma unroll
    for (int i = 0; i < 8; i++)
#pragma unroll
        for (int j = 0; j < 8; j++) acc[i][j] = 0.f;

    const float4 z4 = make_float4(0.f, 0.f, 0.f, 0.f);

    for (int k0 = 0; k0 < K; k0 += 16) {
        float4 av[2], bv[4];
        if (sAk == 1) {
#pragma unroll
            for (int t = 0; t < 2; t++) {
                int f = tid + t * 128;
                int m = f >> 2, kq = f & 3;
                int mm = m0 + m;
                av[t] = (mm < M) ? *(const float4*)&A[(long long)mm * sAm + k0 + kq * 4] : z4;
            }
        } else {
#pragma unroll
            for (int t = 0; t < 2; t++) {
                int f = tid + t * 128;
                int kk = f >> 4, mq = f & 15;
                int mm = m0 + mq * 4;
                av[t] = (mm < M) ? *(const float4*)&A[(long long)(k0 + kk) * sAk + mm] : z4;
            }
        }
#pragma unroll
        for (int t = 0; t < 4; t++) {
            int f = tid + t * 128;
            int kk = f >> 5, nq = f & 31;
            bv[t] = *(const float4*)&Bp[(long long)(k0 + kk) * sBk + n0 + nq * 4];
        }
        __syncthreads();
        if (sAk == 1) {
#pragma unroll
            for (int t = 0; t < 2; t++) {
                int f = tid + t * 128;
                int m = f >> 2, kq = f & 3;
                sA[kq * 4 + 0][m] = av[t].x;
                sA[kq * 4 + 1][m] = av[t].y;
                sA[kq * 4 + 2][m] = av[t].z;
                sA[kq * 4 + 3][m] = av[t].w;
            }
        } else {
#pragma unroll
            for (int t = 0; t < 2; t++) {
                int f = tid + t * 128;
                int kk = f >> 4, mq = f & 15;
                *(float4*)&sA[kk][mq * 4] = av[t];
            }
        }
#pragma unroll
        for (int t = 0; t < 4; t++) {
            int f = tid + t * 128;
            int kk = f >> 5, nq = f & 31;
            *(float4*)&sB[kk][nq * 4] = bv[t];
        }
        __syncthreads();
#pragma unroll
        for (int kk = 0; kk < 16; kk++) {
            float4 a0 = *(const float4*)&sA[kk][mg * 8];
            float4 a1 = *(const float4*)&sA[kk][mg * 8 + 4];
            float4 b0 = *(const float4*)&sB[kk][ng * 8];
            float4 b1 = *(const float4*)&sB[kk][ng * 8 + 4];
            float am[8] = {a0.x, a0.y, a0.z, a0.w, a1.x, a1.y, a1.z, a1.w};
            float bn[8] = {b0.x, b0.y, b0.z, b0.w, b1.x, b1.y, b1.z, b1.w};
#pragma unroll
            for (int i = 0; i < 8; i++)
#pragma unroll
                for (int j = 0; j < 8; j++)
                    acc[i][j] = fmaf(am[i], bn[j], acc[i][j]);
        }
        __syncthreads();
    }

    if (sCn == 1) {
#pragma unroll
        for (int i = 0; i < 8; i++) {
            int mm = m0 + mg * 8 + i;
            if (mm >= M) continue;
            float bb = bias ? bias[mm] : 0.f;
            float v[8];
#pragma unroll
            for (int j = 0; j < 8; j++) {
                float t = acc[i][j] + bb;
                v[j] = act ? silu_f(t) : t;
            }
            float* cp = &Cp[(long long)mm * sCm + n0 + ng * 8];
            *(float4*)cp       = make_float4(v[0], v[1], v[2], v[3]);
            *(float4*)(cp + 4) = make_float4(v[4], v[5], v[6], v[7]);
        }
    } else {
        // m-contiguous store (sCm == 1)
        float bm[8];
#pragma unroll
        for (int i = 0; i < 8; i++) {
            int mm = m0 + mg * 8 + i;
            bm[i] = (bias && mm < M) ? bias[mm] : 0.f;
        }
        if (m0 + mg * 8 < M) {
#pragma unroll
            for (int j = 0; j < 8; j++) {
                int nn = n0 + ng * 8 + j;
                float v[8];
#pragma unroll
                for (int i = 0; i < 8; i++) {
                    float t = acc[i][j] + bm[i];
                    v[i] = act ? silu_f(t) : t;
                }
                float* cp = &Cp[(long long)nn * sCn + m0 + mg * 8];
                *(float4*)cp       = make_float4(v[0], v[1], v[2], v[3]);
                *(float4*)(cp + 4) = make_float4(v[4], v[5], v[6], v[7]);
            }
        }
    }
}

// ---------------- conv 3x3 v2: block 64co x (2 rows x 64px), 128 thr, 8co x 8px/thread ----------------
__global__ void __launch_bounds__(128, 4)
conv3x3_v2(const float* __restrict__ src, float* __restrict__ dst,
           const float* __restrict__ wt,            // transposed [ci*9+tap][256]
           long long srcStride, long long dstStride)
{
    __shared__ __align__(16) float sIn[8][4][68];   // [ci][row][col]; col c <-> x = c-1
    __shared__ __align__(16) float sW[8 * 9][64];   // [ci*9+tap][co]
    int y0  = blockIdx.x * 2;
    int co0 = blockIdx.y * 64;
    const float* sp = src + (long long)blockIdx.z * srcStride;
    float*       dp = dst + (long long)blockIdx.z * dstStride;
    int tid = threadIdx.x;
    int pxg = tid & 15;           // row = pxg>>3, colblk = pxg&7
    int cog = tid >> 4;           // 0..7 -> 8 co each
    int rowsel = pxg >> 3;
    int px0 = (pxg & 7) * 8;

    // zero the constant padding columns (x=-1 -> col 0, x=64 -> col 65) once
    if (tid < 64) {
        int ci = tid >> 3, rr_ = (tid >> 1) & 3, side = tid & 1;
        sIn[ci][rr_][side ? 65 : 0] = 0.f;
    }

    float acc[8][8];
#pragma unroll
    for (int i = 0; i < 8; i++)
#pragma unroll
        for (int j = 0; j < 8; j++) acc[i][j] = 0.f;

    const float4 z4 = make_float4(0.f, 0.f, 0.f, 0.f);

    for (int ci0 = 0; ci0 < 256; ci0 += 8) {
        // stage global loads in registers (overlaps previous chunk's compute)
        float4 ir[4];
#pragma unroll
        for (int t = 0; t < 4; t++) {
            int f = tid + t * 128;          // 0..511
            int ci = f >> 6;
            int rr_ = (f >> 4) & 3;
            int cq = f & 15;
            int yin = y0 - 1 + rr_;
            ir[t] = ((unsigned)yin < 64u)
                  ? *(const float4*)&sp[((long long)(ci0 + ci) << 12) + (yin << 6) + cq * 4]
                  : z4;
        }
        float4 wr[9];
#pragma unroll
        for (int t = 0; t < 9; t++) {
            int f = tid + t * 128;          // 0..1151
            int rrow = f >> 4;              // 0..71
            int cq = f & 15;
            wr[t] = *(const float4*)&wt[(long long)(ci0 * 9 + rrow) * 256 + co0 + cq * 4];
        }
        __syncthreads();
#pragma unroll
        for (int t = 0; t < 4; t++) {
            int f = tid + t * 128;
            int ci = f >> 6;
            int rr_ = (f >> 4) & 3;
            int cq = f & 15;
            float* p = &sIn[ci][rr_][1 + cq * 4];
            p[0] = ir[t].x; p[1] = ir[t].y; p[2] = ir[t].z; p[3] = ir[t].w;
        }
#pragma unroll
        for (int t = 0; t < 9; t++) {
            int f = tid + t * 128;
            int rrow = f >> 4;
            int cq = f & 15;
            *(float4*)&sW[rrow][cq * 4] = wr[t];
        }
        __syncthreads();

#pragma unroll 1
        for (int ci = 0; ci < 8; ci++) {
#pragma unroll
            for (int ky = 0; ky < 3; ky++) {
                const float* rp = &sIn[ci][rowsel + ky][px0];
                float4 r0 = *(const float4*)rp;
                float4 r1 = *(const float4*)(rp + 4);
                float rr[10] = {r0.x, r0.y, r0.z, r0.w, r1.x, r1.y, r1.z, r1.w, rp[8], rp[9]};
#pragma unroll
                for (int kx = 0; kx < 3; kx++) {
                    float4 wa = *(const float4*)&sW[ci * 9 + ky * 3 + kx][cog * 8];
                    float4 wb = *(const float4*)&sW[ci * 9 + ky * 3 + kx][cog * 8 + 4];
                    float wv[8] = {wa.x, wa.y, wa.z, wa.w, wb.x, wb.y, wb.z, wb.w};
#pragma unroll
                    for (int i = 0; i < 8; i++)
#pragma unroll
                        for (int j = 0; j < 8; j++)
                            acc[i][j] = fmaf(wv[i], rr[j + kx], acc[i][j]);
                }
            }
        }
        __syncthreads();
    }

    int y = y0 + rowsel;
#pragma unroll
    for (int i = 0; i < 8; i++) {
        int co = co0 + cog * 8 + i;
        float v[8];
#pragma unroll
        for (int j = 0; j < 8; j++) v[j] = silu_f(acc[i][j]);
        float* cp = &dp[((long long)co << 12) + (y << 6) + px0];
        *(float4*)cp       = make_float4(v[0], v[1], v[2], v[3]);
        *(float4*)(cp + 4) = make_float4(v[4], v[5], v[6], v[7]);
    }
}

// ---------------- deformable sampling: one warp per (b,l,h), lane = dh ----------------
__global__ void msda_kernel(const float* __restrict__ P,
                            const float* __restrict__ rb,
                            float* __restrict__ outp)
{
    int warp = threadIdx.x >> 5;
    int lane = threadIdx.x & 31;
    long long gw = (long long)blockIdx.x * 8 + warp;
    int h = (int)(gw & 7);
    long long bl = gw >> 3;               // b*4096 + l
    long long b  = bl >> 12;
    long long l  = bl & 4095;
    const float* Pl = P + bl * 352;
    const float* Vb = P + b * (long long)NL * 352;
    float rbx = rb[bl * 2 + 0];
    float rby = rb[bl * 2 + 1];

    float lg[4];
    float mx = -1e30f;
#pragma unroll
    for (int p = 0; p < 4; p++) { lg[p] = Pl[320 + h * 4 + p]; mx = fmaxf(mx, lg[p]); }
    float s = 0.f;
#pragma unroll
    for (int p = 0; p < 4; p++) { lg[p] = expf(lg[p] - mx); s += lg[p]; }
    float inv = 1.f / s;

    int hoff = h * 32 + lane;
    float acc = 0.f;
#pragma unroll
    for (int p = 0; p < 4; p++) {
        float ox = Pl[256 + h * 8 + p * 2 + 0];
        float oy = Pl[256 + h * 8 + p * 2 + 1];
        float gx = (rbx + ox * (1.f / 64.f)) * 64.f - 0.5f;
        float gy = (rby + oy * (1.f / 64.f)) * 64.f - 0.5f;
        float x0f = floorf(gx), y0f = floorf(gy);
        int x0 = (int)x0f, y0 = (int)y0f;
        float wx1 = gx - x0f, wy1 = gy - y0f;
        float wx0 = 1.f - wx1, wy0 = 1.f - wy1;

        float v00 = 0.f, v10 = 0.f, v01 = 0.f, v11 = 0.f;
        if ((unsigned)x0       < 64u && (unsigned)y0       < 64u) v00 = Vb[(long long)(y0 * 64 + x0) * 352 + hoff];
        if ((unsigned)(x0 + 1) < 64u && (unsigned)y0       < 64u) v10 = Vb[(long long)(y0 * 64 + x0 + 1) * 352 + hoff];
        if ((unsigned)x0       < 64u && (unsigned)(y0 + 1) < 64u) v01 = Vb[(long long)((y0 + 1) * 64 + x0) * 352 + hoff];
        if ((unsigned)(x0 + 1) < 64u && (unsigned)(y0 + 1) < 64u) v11 = Vb[(long long)((y0 + 1) * 64 + x0 + 1) * 352 + hoff];

        float sv = v00 * (wx0 * wy0) + v10 * (wx1 * wy0) + v01 * (wx0 * wy1) + v11 * (wx1 * wy1);
        acc = fmaf(lg[p] * inv, sv, acc);
    }
    // NCHW output: [b][d][l]
    outp[((long long)b * 256 + hoff) * 4096 + l] = acc;
}

// ---------------- launch ----------------
extern "C" void kernel_launch(void* const* d_in, const int* in_sizes, int n_in,
                              void* d_out, int out_size)
{
    const float* x       = (const float*)d_in[0];
    const float* rb      = (const float*)d_in[1];
    const float* cv1_w   = (const float*)d_in[3];
    const float* m0c1    = (const float*)d_in[4];
    const float* m0c2    = (const float*)d_in[5];
    const float* m1c1    = (const float*)d_in[6];
    const float* m1c2    = (const float*)d_in[7];
    const float* vproj_w = (const float*)d_in[8];
    const float* vproj_b = (const float*)d_in[9];
    const float* off_w   = (const float*)d_in[10];
    const float* off_b   = (const float*)d_in[11];
    const float* aw_w    = (const float*)d_in[12];
    const float* aw_b    = (const float*)d_in[13];
    const float* out_w   = (const float*)d_in[14];
    const float* out_b   = (const float*)d_in[15];
    const float* cv2_w   = (const float*)d_in[16];
    float* out = (float*)d_out;

    float *cat, *tmp, *P, *attn, *WcatT, *bcat, *wtbase;
    cudaGetSymbolAddress((void**)&cat,    g_cat);
    cudaGetSymbolAddress((void**)&tmp,    g_tmp);
    cudaGetSymbolAddress((void**)&P,      g_P);
    cudaGetSymbolAddress((void**)&attn,   g_attn);
    cudaGetSymbolAddress((void**)&WcatT,  g_WcatT);
    cudaGetSymbolAddress((void**)&bcat,   g_bcat);
    cudaGetSymbolAddress((void**)&wtbase, g_wt);

    const long long CATS = (long long)NCAT * NL;
    const long long WTS  = 2304LL * 256;

    // 0) weight prep
    prep_wcat_kernel<<<352, 256>>>(vproj_w, vproj_b, off_w, off_b, aw_w, aw_b);
    transp_w_kernel<<<2304, 256>>>(m0c1, wtbase + 0 * WTS);
    transp_w_kernel<<<2304, 256>>>(m0c2, wtbase + 1 * WTS);
    transp_w_kernel<<<2304, 256>>>(m1c1, wtbase + 2 * WTS);
    transp_w_kernel<<<2304, 256>>>(m1c2, wtbase + 3 * WTS);

    // 1) cv1 (1x1, 512->512, SiLU) -> cat channels [0,512)
    sgemm_v2<<<dim3(32, 8, NB), 128>>>(cv1_w, x, cat, 512, 512,
        512, 1, 512LL * NL, NL, CATS, NL, 1, nullptr, 1);

    // 2) bottleneck convs
    dim3 cgrid(32, 4, NB);
    conv3x3_v2<<<cgrid, 128>>>(cat + 256LL * NL, tmp,              wtbase + 0 * WTS, CATS, (long long)NC * NL);
    conv3x3_v2<<<cgrid, 128>>>(tmp,              cat + 512LL * NL, wtbase + 1 * WTS, (long long)NC * NL, CATS);
    conv3x3_v2<<<cgrid, 128>>>(cat + 512LL * NL, tmp,              wtbase + 2 * WTS, CATS, (long long)NC * NL);
    conv3x3_v2<<<cgrid, 128>>>(tmp,              cat + 768LL * NL, wtbase + 3 * WTS, (long long)NC * NL, CATS);

    // 3) fused projection: P[b][l][352] = q @ [vproj|off|aw] + bias
    sgemm_v2<<<dim3(32, 6, NB), 128>>>(WcatT, cat + 768LL * NL, P, 352, 256,
        256, 1, CATS, NL, (long long)NL * 352, 1, 352, bcat, 0);

    // 4) deformable sampling (writes NCHW attn)
    msda_kernel<<<32768, 256>>>(P, rb, attn);

    // 5) output projection -> cat channels [1024,1280)
    sgemm_v2<<<dim3(32, 4, NB), 128>>>(out_w, attn, cat + 1024LL * NL, 256, 256,
        1, 256, (long long)NC * NL, NL, CATS, NL, 1, out_b, 0);

    // 6) cv2 (1x1, 1280->512, SiLU)
    sgemm_v2<<<dim3(32, 8, NB), 128>>>(cv2_w, cat, out, 512, 1280,
        1280, 1, CATS, NL, 512LL * NL, NL, 1, nullptr, 1);
}

// round 7
// speedup vs baseline: 4.4765x; 2.2060x over previous
#include <cuda_runtime.h>
#include <cuda_bf16.h>
#include <stdint.h>
#include <math.h>

#define NB 8
#define NL 4096

// ================= scratch (device globals) =================
__device__ __align__(1024) __nv_bfloat16 g_xT_hi[(size_t)NB * NL * 512];
__device__ __align__(1024) __nv_bfloat16 g_xT_lo[(size_t)NB * NL * 512];
__device__ __align__(1024) __nv_bfloat16 g_catT_hi[(size_t)NB * NL * 1280];
__device__ __align__(1024) __nv_bfloat16 g_catT_lo[(size_t)NB * NL * 1280];
__device__ __align__(1024) __nv_bfloat16 g_tmpT_hi[(size_t)NB * NL * 256];
__device__ __align__(1024) __nv_bfloat16 g_tmpT_lo[(size_t)NB * NL * 256];
__device__ __align__(1024) __nv_bfloat16 g_sdT_hi[(size_t)NB * NL * 256];
__device__ __align__(1024) __nv_bfloat16 g_sdT_lo[(size_t)NB * NL * 256];
__device__ __align__(1024) float g_P[(size_t)NB * NL * 384];   // 256 val | 64 off | 32 aw | 32 pad
__device__ float g_bias384[384];

// Pre-swizzled weight tiles: [n_tile][stage][ hi 16KB | lo 16KB ]
// tile: 128 co rows x 64 bf16 K; row r at r*128 + (kbyte ^ ((r&7)*16))  (ldmatrix-ready)
__device__ __align__(1024) uint8_t g_Wcv1 [4  * 8  * 32768];   // 512 co, K=512
__device__ __align__(1024) uint8_t g_Wc   [4][2 * 36 * 32768]; // 256 co, K=2304 (9 taps x 256 ci)
__device__ __align__(1024) uint8_t g_Wproj[3  * 4  * 32768];   // 384 co (padded), K=256
__device__ __align__(1024) uint8_t g_Wout [2  * 4  * 32768];   // 256 co, K=256
__device__ __align__(1024) uint8_t g_Wcv2 [4  * 20 * 32768];   // 512 co, K=1280

__device__ __forceinline__ float silu_f(float x) { return x / (1.0f + expf(-x)); }

// ================= PTX helpers (compute_103-safe) =================
__device__ __forceinline__ uint32_t smem_u32(const void* p) {
    uint32_t a;
    asm("{ .reg .u64 t; cvta.to.shared.u64 t, %1; cvt.u32.u64 %0, t; }" : "=r"(a) : "l"(p));
    return a;
}
#define CP_COMMIT() asm volatile("cp.async.commit_group;" ::: "memory")
#define CP_WAIT(n)  asm volatile("cp.async.wait_group %0;" :: "n"(n) : "memory")

__device__ __forceinline__ void cpa16(uint32_t d, const void* s, int sz) {
    asm volatile("cp.async.cg.shared.global [%0], [%1], 16, %2;"
                 :: "r"(d), "l"(s), "r"(sz) : "memory");
}
__device__ __forceinline__ void ldsm4(uint32_t a, uint32_t* r) {
    asm volatile("ldmatrix.sync.aligned.m8n8.x4.shared.b16 {%0,%1,%2,%3}, [%4];"
                 : "=r"(r[0]), "=r"(r[1]), "=r"(r[2]), "=r"(r[3]) : "r"(a));
}
__device__ __forceinline__ void mma16816(float* d, const uint32_t* a, const uint32_t* b) {
    asm volatile("mma.sync.aligned.m16n8k16.row.col.f32.bf16.bf16.f32 "
                 "{%0,%1,%2,%3}, {%4,%5,%6,%7}, {%8,%9}, {%0,%1,%2,%3};"
                 : "+f"(d[0]), "+f"(d[1]), "+f"(d[2]), "+f"(d[3])
                 : "r"(a[0]), "r"(a[1]), "r"(a[2]), "r"(a[3]), "r"(b[0]), "r"(b[1]));
}

// ================= weight prep =================
__device__ __forceinline__ void wstore(uint8_t* dst, int n_stages, int co, int k, float v) {
    int tile = co >> 7, rr = co & 127, st = k >> 6, kk = k & 63;
    __nv_bfloat16 h = __float2bfloat16(v);
    __nv_bfloat16 l = __float2bfloat16(v - __bfloat162float(h));
    size_t base = (size_t)(tile * n_stages + st) * 32768;
    uint32_t off = (uint32_t)(rr * 128 + ((kk * 2) ^ ((rr & 7) * 16)));
    *(__nv_bfloat16*)(dst + base + off) = h;
    *(__nv_bfloat16*)(dst + base + 16384 + off) = l;
}

__global__ void prep_cv1(const float* __restrict__ w) {
    int i = blockIdx.x * 256 + threadIdx.x;            // 512*512
    int co = i >> 9, k = i & 511;
    wstore(g_Wcv1, 8, co, k, w[co * 512 + k]);
}
__global__ void prep_conv(const float* __restrict__ w, uint8_t* __restrict__ dst) {
    int i = blockIdx.x * 256 + threadIdx.x;            // 256*2304
    int co = i / 2304, k = i - co * 2304;
    int tap = k >> 8, ci = k & 255;
    wstore(dst, 36, co, k, w[(co * 256 + ci) * 9 + tap]);
}
__global__ void prep_proj(const float* __restrict__ vw, const float* __restrict__ ow,
                          const float* __restrict__ aww) {
    int i = blockIdx.x * 256 + threadIdx.x;            // 384*256
    int co = i >> 8, k = i & 255;
    float v = (co < 256) ? vw[k * 256 + co]
            : (co < 320) ? ow[k * 64 + (co - 256)]
            : (co < 352) ? aww[k * 32 + (co - 320)] : 0.f;
    wstore(g_Wproj, 4, co, k, v);
}
__global__ void prep_bias(const float* __restrict__ vb, const float* __restrict__ ob,
                          const float* __restrict__ awb) {
    int j = blockIdx.x * 128 + threadIdx.x;
    if (j < 384)
        g_bias384[j] = (j < 256) ? vb[j] : (j < 320) ? ob[j - 256] : (j < 352) ? awb[j - 320] : 0.f;
}
__global__ void prep_outw(const float* __restrict__ w) {
    int i = blockIdx.x * 256 + threadIdx.x;            // 256*256
    int co = i >> 8, k = i & 255;
    wstore(g_Wout, 4, co, k, w[k * 256 + co]);
}
__global__ void prep_cv2(const float* __restrict__ w) {
    int i = blockIdx.x * 256 + threadIdx.x;            // 512*1280
    int co = i / 1280, k = i - co * 1280;
    wstore(g_Wcv2, 20, co, k, w[co * 1280 + k]);
}

// ================= x -> xT hi/lo =================
__global__ void xT_kernel(const float* __restrict__ x) {
    __shared__ float t[32][33];
    int b = blockIdx.z;
    int p0 = blockIdx.x * 32, c0 = blockIdx.y * 32;
    int tx = threadIdx.x, ty = threadIdx.y;            // (32, 8)
    const float* xb = x + (size_t)b * 512 * 4096;
#pragma unroll
    for (int i = 0; i < 4; i++)
        t[ty + i * 8][tx] = xb[(size_t)(c0 + ty + i * 8) * 4096 + p0 + tx];
    __syncthreads();
#pragma unroll
    for (int i = 0; i < 4; i++) {
        int pp = p0 + ty + i * 8, cc = c0 + tx;
        float v = t[tx][ty + i * 8];
        __nv_bfloat16 h = __float2bfloat16(v);
        __nv_bfloat16 l = __float2bfloat16(v - __bfloat162float(h));
        size_t idx = ((size_t)b * 4096 + pp) * 512 + cc;
        g_xT_hi[idx] = h;
        g_xT_lo[idx] = l;
    }
}

// ================= tensor-core GEMM (mma.sync bf16, split hi/lo x3) =================
// D[p][co] = sum_k A[p][k] * W[co][k]; fp32 accum in registers.
// Block 256 thr: M_tile=128 px (blockIdx.y), N_tile=128 co (blockIdx.x), b=blockIdx.z.
// Warp (8): warp_m = w&3 (32 rows), warp_n = w>>2 (64 cols).
// smem/stage: A_hi 16K | A_lo 16K | B_hi 16K | B_lo 16K = 64KB, double buffered.
__global__ void __launch_bounds__(256, 1)
gemm_tc(const __nv_bfloat16* __restrict__ A_hi, const __nv_bfloat16* __restrict__ A_lo,
        int Cs, int c0,
        const uint8_t* __restrict__ W, int n_stages, int conv_mode,
        float* __restrict__ outF,
        __nv_bfloat16* __restrict__ O_hi, __nv_bfloat16* __restrict__ O_lo,
        int CsO, int c0O,
        const float* __restrict__ bias, int out_mode, int act)
{
    extern __shared__ uint8_t dyn[];
    uint8_t* dynp = dyn + ((1024u - (smem_u32(dyn) & 1023u)) & 1023u);
    uint32_t dynb = smem_u32(dynp);

    int tid = threadIdx.x;
    int lane = tid & 31, w = tid >> 5;
    int b = blockIdx.z, n_tile = blockIdx.x;
    int p0 = blockIdx.y * 128;

    const __nv_bfloat16* Ah = A_hi + (size_t)b * NL * Cs + c0;
    const __nv_bfloat16* Al = A_lo + (size_t)b * NL * Cs + c0;
    const uint8_t* Wt = W + (size_t)n_tile * n_stages * 32768;

    // ---- cp.async stage loader ----
    auto issue = [&](int s, int buf) {
        uint32_t bo = dynb + buf * 65536;
        int tap = 0, ky = 0, kx = 0, ci0;
        if (conv_mode) {
            tap = s >> 2; ky = tap / 3; kx = tap - ky * 3;
            ci0 = (s & 3) * 64;
        } else ci0 = s * 64;
#pragma unroll
        for (int t = 0; t < 4; t++) {
            int f = tid + t * 256;                    // 0..1023
            int row = f >> 3, q = f & 7;
            int p = p0 + row;
            int psrc = p, valid = 1;
            if (conv_mode) {
                int yy = (p >> 6) + ky - 1, xx = (p & 63) + kx - 1;
                valid = ((unsigned)yy < 64u) && ((unsigned)xx < 64u);
                psrc = valid ? (p + (ky - 1) * 64 + (kx - 1)) : p;
            }
            uint32_t off = (uint32_t)(row * 128 + ((q * 16) ^ ((row & 7) * 16)));
            int sz = valid ? 16 : 0;
            cpa16(bo + off,         Ah + (size_t)psrc * Cs + ci0 + q * 8, sz);
            cpa16(bo + 16384 + off, Al + (size_t)psrc * Cs + ci0 + q * 8, sz);
        }
        const uint8_t* ws = Wt + (size_t)s * 32768;
#pragma unroll
        for (int t = 0; t < 8; t++) {
            int f = tid + t * 256;                    // 0..2047 -> 32KB (hi+lo)
            cpa16(bo + 32768 + f * 16, ws + f * 16, 16);
        }
    };

    // ---- per-lane ldmatrix bases ----
    int lr = lane & 7, g = lane >> 3;
    int m0w = (w & 3) * 32, n0w = (w >> 2) * 64;
    uint32_t xorv = (uint32_t)(lr * 16);
    int kfixA = (g >> 1) * 16;                         // A: g0 r+0 klo, g1 r+8 klo, g2 r+0 khi, g3 r+8 khi
    int rowA = m0w + (g & 1) * 8 + lr;
    uint32_t aBase[2];
    aBase[0] = dynb + (uint32_t)(rowA * 128);
    aBase[1] = dynb + (uint32_t)((rowA + 16) * 128);
    int kfixB = (g & 1) * 16;                          // B: g0 n+0 klo, g1 n+0 khi, g2 n+8 klo, g3 n+8 khi
    uint32_t bBase[4];
#pragma unroll
    for (int bp = 0; bp < 4; bp++) {
        int rowB = n0w + bp * 16 + (g >> 1) * 8 + lr;
        bBase[bp] = dynb + 32768u + (uint32_t)(rowB * 128);
    }

    float acc[2][8][4];
#pragma unroll
    for (int mi = 0; mi < 2; mi++)
#pragma unroll
        for (int ng = 0; ng < 8; ng++)
#pragma unroll
            for (int q = 0; q < 4; q++) acc[mi][ng][q] = 0.f;

    issue(0, 0); CP_COMMIT();

    for (int s = 0; s < n_stages; s++) {
        int buf = s & 1;
        if (s + 1 < n_stages) { issue(s + 1, buf ^ 1); CP_COMMIT(); CP_WAIT(1); }
        else                  { CP_WAIT(0); }
        __syncthreads();

        uint32_t bo = (uint32_t)(buf * 65536);
#pragma unroll
        for (int kk8 = 0; kk8 < 4; kk8++) {
            int kb = kk8 * 32;
            uint32_t ka  = (uint32_t)((kb + kfixA) ^ (int)xorv);
            uint32_t kbb = (uint32_t)((kb + kfixB) ^ (int)xorv);
            uint32_t ahf[2][4], alf[2][4];
            ldsm4(aBase[0] + bo + ka,          ahf[0]);
            ldsm4(aBase[1] + bo + ka,          ahf[1]);
            ldsm4(aBase[0] + 16384 + bo + ka,  alf[0]);
            ldsm4(aBase[1] + 16384 + bo + ka,  alf[1]);
            uint32_t bhf[4][4], blf[4][4];
#pragma unroll
            for (int bp = 0; bp < 4; bp++) {
                ldsm4(bBase[bp] + bo + kbb,         bhf[bp]);
                ldsm4(bBase[bp] + 16384 + bo + kbb, blf[bp]);
            }
#pragma unroll
            for (int mi = 0; mi < 2; mi++)
#pragma unroll
                for (int ng = 0; ng < 8; ng++) {
                    const uint32_t* bh = &bhf[ng >> 1][(ng & 1) * 2];
                    const uint32_t* bl = &blf[ng >> 1][(ng & 1) * 2];
                    mma16816(acc[mi][ng], ahf[mi], bh);   // hi*hi
                    mma16816(acc[mi][ng], ahf[mi], bl);   // hi*lo
                    mma16816(acc[mi][ng], alf[mi], bh);   // lo*hi
                }
        }
        __syncthreads();
    }

    // ---- epilogue ----
    int prb = p0 + m0w + (lane >> 2);
    int colb = n0w + 2 * (lane & 3);
#pragma unroll
    for (int mi = 0; mi < 2; mi++)
#pragma unroll
        for (int ng = 0; ng < 8; ng++) {
            int cog = n_tile * 128 + colb + ng * 8;
#pragma unroll
            for (int half = 0; half < 2; half++) {
                int pe = prb + mi * 16 + half * 8;
                float v0 = acc[mi][ng][half * 2 + 0];
                float v1 = acc[mi][ng][half * 2 + 1];
                if (out_mode == 0) {
                    if (bias) { v0 += bias[cog]; v1 += bias[cog + 1]; }
                    if (act)  { v0 = silu_f(v0); v1 = silu_f(v1); }
                    __nv_bfloat16 h0 = __float2bfloat16(v0), h1 = __float2bfloat16(v1);
                    __nv_bfloat16 l0 = __float2bfloat16(v0 - __bfloat162float(h0));
                    __nv_bfloat16 l1 = __float2bfloat16(v1 - __bfloat162float(h1));
                    uint32_t hp = (uint32_t)__bfloat16_as_ushort(h0) | ((uint32_t)__bfloat16_as_ushort(h1) << 16);
                    uint32_t lp = (uint32_t)__bfloat16_as_ushort(l0) | ((uint32_t)__bfloat16_as_ushort(l1) << 16);
                    size_t ob = ((size_t)b * NL + pe) * CsO + c0O + cog;
                    *(uint32_t*)(O_hi + ob) = hp;
                    *(uint32_t*)(O_lo + ob) = lp;
                } else if (out_mode == 1) {
                    float2 v;
                    v.x = v0 + bias[cog];
                    v.y = v1 + bias[cog + 1];
                    *(float2*)&outF[((size_t)b * NL + pe) * 384 + cog] = v;
                } else {
                    outF[((size_t)(b * 512 + cog)     << 12) + pe] = silu_f(v0);
                    outF[((size_t)(b * 512 + cog + 1) << 12) + pe] = silu_f(v1);
                }
            }
        }
}

// ================= deformable sampling =================
__global__ void msda_kernel(const float* __restrict__ P, const float* __restrict__ rb)
{
    int warp = threadIdx.x >> 5;
    int lane = threadIdx.x & 31;
    long long gw = (long long)blockIdx.x * 8 + warp;
    int h = (int)(gw & 7);
    long long bl = gw >> 3;
    long long b = bl >> 12;
    const float* Pl = P + bl * 384;
    const float* Vb = P + b * (long long)NL * 384;
    float rbx = rb[bl * 2 + 0];
    float rby = rb[bl * 2 + 1];

    float lg[4];
    float mx = -1e30f;
#pragma unroll
    for (int pp = 0; pp < 4; pp++) { lg[pp] = Pl[320 + h * 4 + pp]; mx = fmaxf(mx, lg[pp]); }
    float s = 0.f;
#pragma unroll
    for (int pp = 0; pp < 4; pp++) { lg[pp] = expf(lg[pp] - mx); s += lg[pp]; }
    float inv = 1.f / s;

    int hoff = h * 32 + lane;
    float acc = 0.f;
#pragma unroll
    for (int pp = 0; pp < 4; pp++) {
        float ox = Pl[256 + h * 8 + pp * 2 + 0];
        float oy = Pl[256 + h * 8 + pp * 2 + 1];
        float gx = (rbx + ox * (1.f / 64.f)) * 64.f - 0.5f;
        float gy = (rby + oy * (1.f / 64.f)) * 64.f - 0.5f;
        float x0f = floorf(gx), y0f = floorf(gy);
        int x0 = (int)x0f, y0 = (int)y0f;
        float wx1 = gx - x0f, wy1 = gy - y0f;
        float wx0 = 1.f - wx1, wy0 = 1.f - wy1;

        float v00 = 0.f, v10 = 0.f, v01 = 0.f, v11 = 0.f;
        if ((unsigned)x0       < 64u && (unsigned)y0       < 64u) v00 = Vb[(long long)(y0 * 64 + x0) * 384 + hoff];
        if ((unsigned)(x0 + 1) < 64u && (unsigned)y0       < 64u) v10 = Vb[(long long)(y0 * 64 + x0 + 1) * 384 + hoff];
        if ((unsigned)x0       < 64u && (unsigned)(y0 + 1) < 64u) v01 = Vb[(long long)((y0 + 1) * 64 + x0) * 384 + hoff];
        if ((unsigned)(x0 + 1) < 64u && (unsigned)(y0 + 1) < 64u) v11 = Vb[(long long)((y0 + 1) * 64 + x0 + 1) * 384 + hoff];

        float sv = v00 * (wx0 * wy0) + v10 * (wx1 * wy0) + v01 * (wx0 * wy1) + v11 * (wx1 * wy1);
        acc = fmaf(lg[pp] * inv, sv, acc);
    }
    __nv_bfloat16 hv = __float2bfloat16(acc);
    __nv_bfloat16 lv = __float2bfloat16(acc - __bfloat162float(hv));
    size_t idx = (size_t)bl * 256 + hoff;
    g_sdT_hi[idx] = hv;
    g_sdT_lo[idx] = lv;
}

// ================= launch =================
extern "C" void kernel_launch(void* const* d_in, const int* in_sizes, int n_in,
                              void* d_out, int out_size)
{
    const float* x       = (const float*)d_in[0];
    const float* rb      = (const float*)d_in[1];
    const float* cv1_w   = (const float*)d_in[3];
    const float* m0c1    = (const float*)d_in[4];
    const float* m0c2    = (const float*)d_in[5];
    const float* m1c1    = (const float*)d_in[6];
    const float* m1c2    = (const float*)d_in[7];
    const float* vproj_w = (const float*)d_in[8];
    const float* vproj_b = (const float*)d_in[9];
    const float* off_w   = (const float*)d_in[10];
    const float* off_b   = (const float*)d_in[11];
    const float* aw_w    = (const float*)d_in[12];
    const float* aw_b    = (const float*)d_in[13];
    const float* out_w   = (const float*)d_in[14];
    const float* out_b   = (const float*)d_in[15];
    const float* cv2_w   = (const float*)d_in[16];
    float* out = (float*)d_out;

    __nv_bfloat16 *xT_h, *xT_l, *catT_h, *catT_l, *tmpT_h, *tmpT_l, *sdT_h, *sdT_l;
    float *P, *bias384;
    uint8_t *Wcv1, *Wc, *Wproj, *Wout, *Wcv2;
    cudaGetSymbolAddress((void**)&xT_h,   g_xT_hi);
    cudaGetSymbolAddress((void**)&xT_l,   g_xT_lo);
    cudaGetSymbolAddress((void**)&catT_h, g_catT_hi);
    cudaGetSymbolAddress((void**)&catT_l, g_catT_lo);
    cudaGetSymbolAddress((void**)&tmpT_h, g_tmpT_hi);
    cudaGetSymbolAddress((void**)&tmpT_l, g_tmpT_lo);
    cudaGetSymbolAddress((void**)&sdT_h,  g_sdT_hi);
    cudaGetSymbolAddress((void**)&sdT_l,  g_sdT_lo);
    cudaGetSymbolAddress((void**)&P,      g_P);
    cudaGetSymbolAddress((void**)&bias384,g_bias384);
    cudaGetSymbolAddress((void**)&Wcv1,   g_Wcv1);
    cudaGetSymbolAddress((void**)&Wc,     g_Wc);
    cudaGetSymbolAddress((void**)&Wproj,  g_Wproj);
    cudaGetSymbolAddress((void**)&Wout,   g_Wout);
    cudaGetSymbolAddress((void**)&Wcv2,   g_Wcv2);

    const int SMEM_DYN = 2 * 65536 + 1024;
    cudaFuncSetAttribute(gemm_tc, cudaFuncAttributeMaxDynamicSharedMemorySize, SMEM_DYN);

    const size_t WCS = 2ull * 36 * 32768;

    // ---- prep ----
    prep_cv1 <<<1024, 256>>>(cv1_w);
    prep_conv<<<2304, 256>>>(m0c1, Wc + 0 * WCS);
    prep_conv<<<2304, 256>>>(m0c2, Wc + 1 * WCS);
    prep_conv<<<2304, 256>>>(m1c1, Wc + 2 * WCS);
    prep_conv<<<2304, 256>>>(m1c2, Wc + 3 * WCS);
    prep_proj<<<384, 256>>>(vproj_w, off_w, aw_w);
    prep_bias<<<3, 128>>>(vproj_b, off_b, aw_b);
    prep_outw<<<256, 256>>>(out_w);
    prep_cv2 <<<2560, 256>>>(cv2_w);
    xT_kernel<<<dim3(128, 16, NB), dim3(32, 8)>>>(x);

    // ---- cv1: xT[512] -> catT[0:512) (SiLU) ----
    gemm_tc<<<dim3(4, 32, NB), 256, SMEM_DYN>>>(xT_h, xT_l, 512, 0, Wcv1, 8, 0,
        nullptr, catT_h, catT_l, 1280, 0, nullptr, 0, 1);
    // ---- conv0: catT b[256:512) -> tmpT (SiLU) ----
    gemm_tc<<<dim3(2, 32, NB), 256, SMEM_DYN>>>(catT_h, catT_l, 1280, 256, Wc + 0 * WCS, 36, 1,
        nullptr, tmpT_h, tmpT_l, 256, 0, nullptr, 0, 1);
    // ---- conv1: tmpT -> catT b1[512:768) (SiLU) ----
    gemm_tc<<<dim3(2, 32, NB), 256, SMEM_DYN>>>(tmpT_h, tmpT_l, 256, 0, Wc + 1 * WCS, 36, 1,
        nullptr, catT_h, catT_l, 1280, 512, nullptr, 0, 1);
    // ---- conv2: catT b1 -> tmpT (SiLU) ----
    gemm_tc<<<dim3(2, 32, NB), 256, SMEM_DYN>>>(catT_h, catT_l, 1280, 512, Wc + 2 * WCS, 36, 1,
        nullptr, tmpT_h, tmpT_l, 256, 0, nullptr, 0, 1);
    // ---- conv3: tmpT -> catT b2[768:1024) (SiLU) ----
    gemm_tc<<<dim3(2, 32, NB), 256, SMEM_DYN>>>(tmpT_h, tmpT_l, 256, 0, Wc + 3 * WCS, 36, 1,
        nullptr, catT_h, catT_l, 1280, 768, nullptr, 0, 1);
    // ---- proj: catT b2 -> P[b][p][384] (+bias) ----
    gemm_tc<<<dim3(3, 32, NB), 256, SMEM_DYN>>>(catT_h, catT_l, 1280, 768, Wproj, 4, 0,
        P, nullptr, nullptr, 0, 0, bias384, 1, 0);
    // ---- deformable sampling -> sdT hi/lo ----
    msda_kernel<<<32768, 256>>>(P, rb);
    // ---- out projection: sdT -> catT attn[1024:1280) (+out_b) ----
    gemm_tc<<<dim3(2, 32, NB), 256, SMEM_DYN>>>(sdT_h, sdT_l, 256, 0, Wout, 4, 0,
        nullptr, catT_h, catT_l, 1280, 1024, out_b, 0, 0);
    // ---- cv2: catT[1280] -> out fp32 NCHW (SiLU) ----
    gemm_tc<<<dim3(4, 32, NB), 256, SMEM_DYN>>>(catT_h, catT_l, 1280, 0, Wcv2, 20, 0,
        out, nullptr, nullptr, 0, 0, nullptr, 2, 1);
}